// round 8
// baseline (speedup 1.0000x reference)
#include <cuda_runtime.h>
#include <stdint.h>

#define NMAX 33600
#define GMAX 128
#define CMAX 80
#define TPB 256
#define TK 10
#define GTILE 16
#define SPLIT 16
#define NW (TPB / 32)
#define CAP 768
#define SLICEMAX 2104
#define TOTK (SPLIT * TK)               // 160 partial keys per gt per list
#define KM 5                            // keys per lane in merge (160/32)
#define EPSF 1e-7f
#define INF_F 100000.0f
#define BIG_F 100000000.0f
#define CRAD 2.5f
#define NWORDS ((NMAX + 31) / 32)
#define FULLM 0xffffffffu

typedef unsigned long long ull;

// ---- scratch as __device__ globals (allocation-free rule) ----
__device__ float    g_D[(size_t)CMAX * NMAX];    // logit(p), class-major (used classes)
__device__ float    g_sumL1[NMAX];
__device__ float4   g_ic4[(size_t)GMAX * NMAX / 2];   // {iou,cost} pairs, 16B-aligned
#define G_IC ((float2*)g_ic4)
__device__ unsigned g_valid[NWORDS];
__device__ int      g_cnt[NMAX];
__device__ int      g_mg[NMAX];
__device__ int      g_flags[CMAX];
__device__ int      g_done[GMAX];
__device__ ull      g_piou [GMAX * TOTK];
__device__ ull      g_pcost[GMAX * TOTK];

// monotone float->uint (ascending order preserved)
__device__ __forceinline__ unsigned fkey(float f) {
    unsigned u = __float_as_uint(f);
    return (u & 0x80000000u) ? ~u : (u | 0x80000000u);
}
__device__ __forceinline__ float unfkey(unsigned k) {
    unsigned u = (k & 0x80000000u) ? (k ^ 0x80000000u) : ~k;
    return __uint_as_float(u);
}

__device__ __forceinline__ ull umin64(ull a, ull b) { return a < b ? a : b; }

// -------- kSetup --------
__global__ void kSetup(const int* __restrict__ gtl, int N, int G) {
    int tid = threadIdx.x;
    int i = blockIdx.x * blockDim.x + tid;
    if (i < N) { g_cnt[i] = 0; g_mg[i] = 0x7fffffff; }
    if (i < NWORDS) g_valid[i] = 0u;
    if (blockIdx.x == 0) {
        if (tid < CMAX) g_flags[tid] = 0;
        if (tid < GMAX) g_done[tid] = 0;
        __syncthreads();
        for (int j = tid; j < G; j += TPB) g_flags[gtl[j]] = 1;
    }
}

// -------- kA80: fused logit + sumL1 (C==80 fast path) --------
__global__ void __launch_bounds__(TPB) kA80(const float* __restrict__ ps, int N) {
    __shared__ float s[32 * 81];
    __shared__ float part[8][33];
    int tid = threadIdx.x;
    int n0 = blockIdx.x * 32;
    int rows = min(32, N - n0);
    for (int i = tid; i < rows * 80; i += TPB) {
        int r = i / 80, c = i - r * 80;
        s[r * 81 + c] = ps[(size_t)n0 * 80 + i];
    }
    __syncthreads();
    int lane = tid & 31, w = tid >> 5;
    int n = n0 + lane;
    if (lane < rows) {
        float prod0 = 1.f, prod1 = 1.f;
        #pragma unroll
        for (int j = 0; j < 10; j++) {
            int c = w + j * 8;
            float p = s[lane * 81 + c];
            float q = 1.f - p;
            if (j < 5) prod0 *= q; else prod1 *= q;
            if (g_flags[c])
                g_D[(size_t)c * N + n] = __logf(__fdividef(p, q));
        }
        part[w][lane] = __logf(prod0) + __logf(prod1);
    }
    __syncthreads();
    if (w == 0 && lane < rows) {
        float ssum = 0.f;
        #pragma unroll
        for (int k = 0; k < 8; k++) ssum += part[k][lane];
        g_sumL1[n] = ssum;
    }
}

// generic fallback
__global__ void kAgen(const float* __restrict__ ps, int N, int C) {
    int n = blockIdx.x * blockDim.x + threadIdx.x;
    if (n >= N) return;
    float ssum = 0.f;
    for (int c = 0; c < C; c++) {
        float p = ps[(size_t)n * C + c];
        float L  = fmaxf(__logf(p), -100.f);
        float L1 = fmaxf(__logf(1.f - p), -100.f);
        g_D[(size_t)c * N + n] = L - L1;
        ssum += L1;
    }
    g_sumL1[n] = ssum;
}

// -------- kB: pairwise IoU + cost, single float2 store per pair --------
__global__ void __launch_bounds__(TPB) kB(
    const float* __restrict__ priors, const float* __restrict__ dec,
    const float* __restrict__ gtb, const int* __restrict__ gtl,
    int N, int G)
{
    __shared__ float4 sg0[GTILE];
    __shared__ float4 sg1[GTILE];
    int tid = threadIdx.x;
    int g0 = blockIdx.y * GTILE;
    int gcnt = min(GTILE, G - g0);
    if (tid < gcnt) {
        int g = g0 + tid;
        float x0 = gtb[4*g+0], y0 = gtb[4*g+1], x1 = gtb[4*g+2], y1 = gtb[4*g+3];
        sg0[tid] = make_float4(x0, y0, x1, y1);
        float gcx = (x0 + x1) * 0.5f, gcy = (y0 + y1) * 0.5f;
        float area = fmaxf(x1 - x0, 0.f) * fmaxf(y1 - y0, 0.f);
        sg1[tid] = make_float4(gcx, gcy, area, __int_as_float(gtl[g]));
    }
    __syncthreads();

    int n = blockIdx.x * blockDim.x + tid;
    if (n >= N) return;
    float4 pq = ((const float4*)priors)[n];
    float px = pq.x, py = pq.y;
    float a1 = px + CRAD * pq.z, a2 = px - CRAD * pq.z;
    float b1 = py + CRAD * pq.w, b2 = py - CRAD * pq.w;
    float4 dq = ((const float4*)dec)[n];
    float dx0 = dq.x, dy0 = dq.y, dx1 = dq.z, dy1 = dq.w;
    float aa = fmaxf(dx1 - dx0, 0.f) * fmaxf(dy1 - dy0, 0.f);
    float sL1 = g_sumL1[n];

    bool vacc = false;
    #pragma unroll
    for (int gi = 0; gi < GTILE; gi++) {
        if (gi < gcnt) {
            float4 q0 = sg0[gi];
            float4 q1 = sg1[gi];
            int g = g0 + gi;
            float m1 = fminf(fminf(px - q0.x, py - q0.y), fminf(q0.z - px, q0.w - py));
            float m2 = fminf(fminf(a1 - q1.x, b1 - q1.y), fminf(q1.x - a2, q1.y - b2));
            bool ing = m1 > 0.f, inc = m2 > 0.f;
            vacc = vacc || ing || inc;
            float w = fmaxf(fminf(dx1, q0.z) - fmaxf(dx0, q0.x), 0.f);
            float h = fmaxf(fminf(dy1, q0.w) - fmaxf(dy0, q0.y), 0.f);
            float inter = w * h;
            float uni = fmaxf(aa + q1.z - inter, EPSF);
            float iou = __fdividef(inter, uni);
            int lbl = __float_as_int(q1.w);
            float cls = -g_D[(size_t)lbl * N + n] - sL1;
            float cost = cls - 3.0f * __logf(iou + EPSF);
            if (!(ing && inc)) cost += INF_F;
            G_IC[(size_t)g * N + n] = make_float2(iou, cost);
        }
    }
    unsigned m = __ballot_sync(__activemask(), vacc);
    if ((tid & 31) == 0 && m) atomicOr(&g_valid[n >> 5], m);
}

// -------- kTopPart: grid (G, SPLIT). One global pass: mask + smem cache +
//          top-2 sample; threshold; compact from smem; extract; merge. ----
__global__ void __launch_bounds__(TPB) kTopPart(int N) {
    __shared__ float2 sval[SLICEMAX];
    __shared__ ull    sbuf[2][CAP];
    __shared__ float  ssamp[2][16];
    __shared__ float  sT[2];
    __shared__ int    scnt[2];
    __shared__ ull    skeep[2][TK];
    __shared__ int    sfl, sdk;

    int g = blockIdx.x, s = blockIdx.y;
    int tid = threadIdx.x, lane = tid & 31, w = tid >> 5;
    int len = (((N + SPLIT - 1) / SPLIT) + 3) & ~3;
    int n0 = s * len;
    int n1 = min(N, n0 + len);
    int total = n1 - n0;
    if (total < 0) total = 0;
    const float2* col = G_IC + (size_t)g * N;

    if (tid < 2) scnt[tid] = 0;

    // ---- phase A: single global pass; mask once; cache to smem; sample top-2
    float i1 = -1.f, i2 = -1.f;          // two largest masked ious
    float c1 = 3.0e38f, c2 = 3.0e38f;    // two smallest masked costs
    int tfull = total & ~1;
    for (int idx = tid * 2; idx < tfull; idx += TPB * 2) {
        int n = n0 + idx;
        float4 v = *reinterpret_cast<const float4*>(col + n);
        unsigned wv = g_valid[n >> 5] >> (n & 31);
        float io0 = (wv & 1u) ? v.x : 0.f,  co0 = (wv & 1u) ? v.y : BIG_F;
        float io1 = (wv & 2u) ? v.z : 0.f,  co1 = (wv & 2u) ? v.w : BIG_F;
        sval[idx]     = make_float2(io0, co0);
        sval[idx + 1] = make_float2(io1, co1);
        if (io0 > i2) { if (io0 > i1) { i2 = i1; i1 = io0; } else i2 = io0; }
        if (io1 > i2) { if (io1 > i1) { i2 = i1; i1 = io1; } else i2 = io1; }
        if (co0 < c2) { if (co0 < c1) { c2 = c1; c1 = co0; } else c2 = co0; }
        if (co1 < c2) { if (co1 < c1) { c2 = c1; c1 = co1; } else c2 = co1; }
    }
    if (tid == 0 && tfull < total) {
        int n = n0 + tfull;
        float2 p = col[n];
        bool vd = (g_valid[n >> 5] >> (n & 31)) & 1u;
        float io = vd ? p.x : 0.f, co = vd ? p.y : BIG_F;
        sval[tfull] = make_float2(io, co);
        if (io > i2) { if (io > i1) { i2 = i1; i1 = io; } else i2 = io; }
        if (co < c2) { if (co < c1) { c2 = c1; c1 = co; } else c2 = co; }
    }
    // warp-merge top-2 (once)
    #pragma unroll
    for (int off = 16; off; off >>= 1) {
        float oi1 = __shfl_xor_sync(FULLM, i1, off);
        float oi2 = __shfl_xor_sync(FULLM, i2, off);
        float ni1 = fmaxf(i1, oi1);
        float ni2 = fmaxf(fminf(i1, oi1), fmaxf(i2, oi2));
        i1 = ni1; i2 = ni2;
        float oc1 = __shfl_xor_sync(FULLM, c1, off);
        float oc2 = __shfl_xor_sync(FULLM, c2, off);
        float nc1 = fminf(c1, oc1);
        float nc2 = fminf(fmaxf(c1, oc1), fminf(c2, oc2));
        c1 = nc1; c2 = nc2;
    }
    if (lane == 0) {
        ssamp[0][2 * w] = i1; ssamp[0][2 * w + 1] = i2;
        ssamp[1][2 * w] = c1; ssamp[1][2 * w + 1] = c2;
    }
    __syncthreads();

    // ---- threshold: 10th best of 16 samples (ties broken by lane) ----
    if (w < 2) {
        float v = (lane < 16) ? ssamp[w][lane] : (w ? 3.0e38f : -1.f);
        int cnt = 0;
        #pragma unroll
        for (int j = 0; j < 16; j++) {
            float o = __shfl_sync(FULLM, v, j);
            bool better = (w == 0) ? (o > v) : (o < v);
            cnt += (better || (o == v && j < lane)) ? 1 : 0;
        }
        unsigned sel = __ballot_sync(FULLM, lane < 16 && cnt == 9);
        int l = __ffs(sel) - 1;
        float T = __shfl_sync(FULLM, v, l);
        if (lane == 0) sT[w] = T;
    }
    __syncthreads();
    float Ti = sT[0], Tc = sT[1];

    // ---- phase B: compact from smem (2 compares/elem, rare appends) ----
    for (int idx = tid; idx < total; idx += TPB) {
        float2 p = sval[idx];
        if (p.x >= Ti) {
            int n = n0 + idx;
            ull key = ((ull)(unsigned)~fkey(p.x) << 32) | (unsigned)n;
            int q = atomicAdd(&scnt[0], 1); if (q < CAP) sbuf[0][q] = key;
        }
        if (p.y <= Tc) {
            int n = n0 + idx;
            ull key = ((ull)fkey(p.y) << 32) | (unsigned)n;
            int q = atomicAdd(&scnt[1], 1); if (q < CAP) sbuf[1][q] = key;
        }
    }
    __syncthreads();

    // ---- exact top-10 extraction from buffers ----
    if (w < 2) {
        int cnt = min(scnt[w], CAP);
        ull* buf = sbuf[w];
        for (int r = 0; r < TK; r++) {
            ull m = ~0ULL;
            for (int i = lane; i < cnt; i += 32) m = umin64(m, buf[i]);
            #pragma unroll
            for (int off = 16; off; off >>= 1)
                m = umin64(m, __shfl_xor_sync(FULLM, m, off));
            for (int i = lane; i < cnt; i += 32)
                if (buf[i] == m) buf[i] = ~0ULL;
            if (lane == 0) skeep[w][r] = m;
        }
    }
    __syncthreads();
    if (w == 0 && lane < TK) g_piou [(g * SPLIT + s) * TK + lane] = skeep[0][lane];
    if (w == 1 && lane < TK) g_pcost[(g * SPLIT + s) * TK + lane] = skeep[1][lane];
    __syncthreads();
    if (tid == 0) {
        __threadfence();
        int old = atomicAdd(&g_done[g], 1);
        sfl = (old == gridDim.y - 1);
    }
    __syncthreads();
    if (!sfl) return;

    // ---- last block for g: merge 160 keys per list ----
    if (w < 2) {
        const ull* src = (w == 0) ? &g_piou[g * TOTK] : &g_pcost[g * TOTK];
        ull kk[KM];
        #pragma unroll
        for (int j = 0; j < KM; j++) {
            int idx = lane + 32 * j;
            kk[j] = (idx < TOTK) ? __ldcg(&src[idx]) : ~0ULL;
        }
        for (int r = 0; r < TK; r++) {
            ull m = kk[0];
            #pragma unroll
            for (int j = 1; j < KM; j++) m = umin64(m, kk[j]);
            #pragma unroll
            for (int off = 16; off; off >>= 1)
                m = umin64(m, __shfl_xor_sync(FULLM, m, off));
            bool cleared = false;
            #pragma unroll
            for (int j = 0; j < KM; j++) {
                if (!cleared && kk[j] == m) { kk[j] = ~0ULL; cleared = true; }
            }
            if (lane == 0) skeep[w][r] = m;
        }
    }
    __syncthreads();
    if (tid == 0) {
        float ssum = 0.f;
        #pragma unroll
        for (int r = 0; r < TK; r++) {
            ull k = skeep[0][r];
            if (k != ~0ULL) ssum += unfkey(~(unsigned)(k >> 32));
        }
        int dk = (int)ssum;
        sdk = dk < 1 ? 1 : (dk > TK ? TK : dk);
    }
    __syncthreads();
    if (tid < sdk) {
        ull k = skeep[1][tid];
        if (k != ~0ULL) {
            int n = (int)(unsigned)k;
            atomicAdd(&g_cnt[n], 1);
            atomicMin(&g_mg[n], g);
        }
    }
}

// -------- finalize --------
__global__ void kFinal(float* __restrict__ out, int N, int G) {
    int n = blockIdx.x * blockDim.x + threadIdx.x;
    if (n >= N) return;
    int c = g_cnt[n];
    bool val = (g_valid[n >> 5] >> (n & 31)) & 1u;
    float gi = 0.f, lb = -1.f, io = -INF_F;
    if (c == 1) {
        int g = g_mg[n];
        gi = (float)g; lb = 1.f;
        io = val ? G_IC[(size_t)g * N + n].x : 0.f;
    } else if (c > 1) {
        lb = 1.f;
        if (!val) { gi = 0.f; io = 0.f; }
        else {
            float best = 3.4e38f; int bg = 0;
            for (int g = 0; g < G; g++) {
                float v = G_IC[(size_t)g * N + n].y;
                if (v < best) { best = v; bg = g; }
            }
            gi = (float)bg;
            io = G_IC[(size_t)bg * N + n].x;
        }
    }
    out[n] = gi;
    out[N + n] = lb;
    out[2 * N + n] = io;
}

extern "C" void kernel_launch(void* const* d_in, const int* in_sizes, int n_in,
                              void* d_out, int out_size) {
    const float* ps  = (const float*)d_in[0];
    const float* pri = (const float*)d_in[1];
    const float* dec = (const float*)d_in[2];
    const float* gtb = (const float*)d_in[3];
    const int*   gtl = (const int*)d_in[4];
    int N = in_sizes[1] / 4;
    int G = in_sizes[3] / 4;
    int C = in_sizes[0] / N;
    if (N > NMAX || G > GMAX || C > CMAX) return;
    float* out = (float*)d_out;
    (void)out_size; (void)n_in;

    kSetup<<<(N + TPB - 1) / TPB, TPB>>>(gtl, N, G);
    if (C == 80)
        kA80<<<(N + 31) / 32, TPB>>>(ps, N);
    else
        kAgen<<<(N + TPB - 1) / TPB, TPB>>>(ps, N, C);
    dim3 gb((N + TPB - 1) / TPB, (G + GTILE - 1) / GTILE);
    kB<<<gb, TPB>>>(pri, dec, gtb, gtl, N, G);
    dim3 gt(G, SPLIT);
    kTopPart<<<gt, TPB>>>(N);
    kFinal<<<(N + TPB - 1) / TPB, TPB>>>(out, N, G);
}

// round 9
// speedup vs baseline: 1.6654x; 1.6654x over previous
#include <cuda_runtime.h>
#include <stdint.h>

#define NMAX 33600
#define GMAX 128
#define CMAX 80
#define TPB 256
#define TK 10
#define GTILE 16
#define SPLIT 8
#define NW (TPB / 32)
#define CAP 768
#define TOTK (SPLIT * TK)               // 80 partial keys per gt per list
#define EPSF 1e-7f
#define INF_F 100000.0f
#define BIG_F 100000000.0f
#define CRAD 2.5f
#define NWORDS ((NMAX + 31) / 32)
#define FULLM 0xffffffffu

typedef unsigned long long ull;

// ---- scratch as __device__ globals (allocation-free rule) ----
__device__ float    g_D[(size_t)CMAX * NMAX];    // logit(p), class-major
__device__ float    g_sumL1[NMAX];
__device__ float4   g_ic4[(size_t)GMAX * NMAX / 2];   // {iou,cost} pairs, 16B-aligned
#define G_IC ((float2*)g_ic4)
__device__ unsigned g_valid[NWORDS];
__device__ int      g_cnt[NMAX];
__device__ int      g_mg[NMAX];
__device__ int      g_done[GMAX];
__device__ ull      g_piou [GMAX * TOTK];
__device__ ull      g_pcost[GMAX * TOTK];

// monotone float->uint (ascending order preserved)
__device__ __forceinline__ unsigned fkey(float f) {
    unsigned u = __float_as_uint(f);
    return (u & 0x80000000u) ? ~u : (u | 0x80000000u);
}
__device__ __forceinline__ float unfkey(unsigned k) {
    unsigned u = (k & 0x80000000u) ? (k ^ 0x80000000u) : ~k;
    return __uint_as_float(u);
}

__device__ __forceinline__ ull umin64(ull a, ull b) { return a < b ? a : b; }

// -------- kA80: fused init + logit + sumL1 (C==80 fast path) --------
// grid = ceil(N/32) blocks; block b also zeroes valid word b, cnt/mg for its
// 32 anchors, and done[b] for b < GMAX.
__global__ void __launch_bounds__(TPB) kA80(const float* __restrict__ ps, int N) {
    __shared__ float s[32 * 81];
    __shared__ float part[8][33];
    int tid = threadIdx.x;
    int n0 = blockIdx.x * 32;
    int rows = min(32, N - n0);

    // fused setup (indices disjoint from compute outputs)
    if (tid < 32 && tid < rows) { g_cnt[n0 + tid] = 0; g_mg[n0 + tid] = 0x7fffffff; }
    if (tid == 32) g_valid[blockIdx.x] = 0u;
    if (tid == 33 && (int)blockIdx.x < GMAX) g_done[blockIdx.x] = 0;

    for (int i = tid; i < rows * 80; i += TPB) {
        int r = i / 80, c = i - r * 80;
        s[r * 81 + c] = ps[n0 * 80 + i];
    }
    __syncthreads();
    int lane = tid & 31, w = tid >> 5;
    int n = n0 + lane;
    if (lane < rows) {
        float prod0 = 1.f, prod1 = 1.f;
        #pragma unroll
        for (int j = 0; j < 10; j++) {
            int c = w + j * 8;
            float p = s[lane * 81 + c];
            float q = 1.f - p;
            if (j < 5) prod0 *= q; else prod1 *= q;
            g_D[c * N + n] = __logf(__fdividef(p, q));
        }
        part[w][lane] = __logf(prod0) + __logf(prod1);
    }
    __syncthreads();
    if (w == 0 && lane < rows) {
        float ssum = 0.f;
        #pragma unroll
        for (int k = 0; k < 8; k++) ssum += part[k][lane];
        g_sumL1[n] = ssum;
    }
}

// -------- generic fallbacks (not used for this problem's shapes) --------
__global__ void kSetup(int N, int G) {
    int i = blockIdx.x * blockDim.x + threadIdx.x;
    if (i < N) { g_cnt[i] = 0; g_mg[i] = 0x7fffffff; }
    if (i < NWORDS) g_valid[i] = 0u;
    if (i < GMAX) g_done[i] = 0;
}
__global__ void kAgen(const float* __restrict__ ps, int N, int C) {
    int n = blockIdx.x * blockDim.x + threadIdx.x;
    if (n >= N) return;
    float ssum = 0.f;
    for (int c = 0; c < C; c++) {
        float p = ps[(size_t)n * C + c];
        float L  = fmaxf(__logf(p), -100.f);
        float L1 = fmaxf(__logf(1.f - p), -100.f);
        g_D[c * N + n] = L - L1;
        ssum += L1;
    }
    g_sumL1[n] = ssum;
}

// -------- kB: pairwise IoU + cost, single float2 store per pair --------
__global__ void __launch_bounds__(TPB) kB(
    const float* __restrict__ priors, const float* __restrict__ dec,
    const float* __restrict__ gtb, const int* __restrict__ gtl,
    int N, int G)
{
    __shared__ float4 sg0[GTILE];
    __shared__ float4 sg1[GTILE];
    int tid = threadIdx.x;
    int g0 = blockIdx.y * GTILE;
    int gcnt = min(GTILE, G - g0);
    if (tid < gcnt) {
        int g = g0 + tid;
        float x0 = gtb[4*g+0], y0 = gtb[4*g+1], x1 = gtb[4*g+2], y1 = gtb[4*g+3];
        sg0[tid] = make_float4(x0, y0, x1, y1);
        float gcx = (x0 + x1) * 0.5f, gcy = (y0 + y1) * 0.5f;
        float area = fmaxf(x1 - x0, 0.f) * fmaxf(y1 - y0, 0.f);
        // pre-bake label*N so the inner loop reads it directly (int)
        sg1[tid] = make_float4(gcx, gcy, area, __int_as_float(gtl[g] * N));
    }
    __syncthreads();

    int n = blockIdx.x * blockDim.x + tid;
    if (n >= N) return;
    float4 pq = ((const float4*)priors)[n];
    float px = pq.x, py = pq.y;
    float a1 = px + CRAD * pq.z, a2 = px - CRAD * pq.z;
    float b1 = py + CRAD * pq.w, b2 = py - CRAD * pq.w;
    float4 dq = ((const float4*)dec)[n];
    float dx0 = dq.x, dy0 = dq.y, dx1 = dq.z, dy1 = dq.w;
    float aa = fmaxf(dx1 - dx0, 0.f) * fmaxf(dy1 - dy0, 0.f);
    float sL1 = g_sumL1[n];

    bool vacc = false;
    int base = g0 * N + n;                 // int offset, bumped by N per gi
    if (gcnt == GTILE) {
        #pragma unroll
        for (int gi = 0; gi < GTILE; gi++) {
            float4 q0 = sg0[gi];
            float4 q1 = sg1[gi];
            float m1 = fminf(fminf(px - q0.x, py - q0.y), fminf(q0.z - px, q0.w - py));
            float m2 = fminf(fminf(a1 - q1.x, b1 - q1.y), fminf(q1.x - a2, q1.y - b2));
            bool ing = m1 > 0.f, inc = m2 > 0.f;
            vacc = vacc || ing || inc;
            float w = fmaxf(fminf(dx1, q0.z) - fmaxf(dx0, q0.x), 0.f);
            float h = fmaxf(fminf(dy1, q0.w) - fmaxf(dy0, q0.y), 0.f);
            float inter = w * h;
            float uni = fmaxf(aa + q1.z - inter, EPSF);
            float iou = __fdividef(inter, uni);
            float cls = -g_D[__float_as_int(q1.w) + n] - sL1;
            float cost = cls - 3.0f * __logf(iou + EPSF);
            if (!(ing && inc)) cost += INF_F;
            G_IC[base] = make_float2(iou, cost);
            base += N;
        }
    } else {
        for (int gi = 0; gi < gcnt; gi++) {
            float4 q0 = sg0[gi];
            float4 q1 = sg1[gi];
            float m1 = fminf(fminf(px - q0.x, py - q0.y), fminf(q0.z - px, q0.w - py));
            float m2 = fminf(fminf(a1 - q1.x, b1 - q1.y), fminf(q1.x - a2, q1.y - b2));
            bool ing = m1 > 0.f, inc = m2 > 0.f;
            vacc = vacc || ing || inc;
            float w = fmaxf(fminf(dx1, q0.z) - fmaxf(dx0, q0.x), 0.f);
            float h = fmaxf(fminf(dy1, q0.w) - fmaxf(dy0, q0.y), 0.f);
            float inter = w * h;
            float uni = fmaxf(aa + q1.z - inter, EPSF);
            float iou = __fdividef(inter, uni);
            float cls = -g_D[__float_as_int(q1.w) + n] - sL1;
            float cost = cls - 3.0f * __logf(iou + EPSF);
            if (!(ing && inc)) cost += INF_F;
            G_IC[base] = make_float2(iou, cost);
            base += N;
        }
    }
    unsigned m = __ballot_sync(__activemask(), vacc);
    if ((tid & 31) == 0 && m) atomicOr(&g_valid[n >> 5], m);
}

// -------- kTopPart: grid (G, SPLIT). float-threshold sampling + compaction.
//          Last block per g merges + dynamic_k + atomics. (R7 logic) ----
__global__ void __launch_bounds__(TPB) kTopPart(int N) {
    __shared__ ull   sbuf[2][CAP];
    __shared__ float ssamp[2][16];
    __shared__ float sT[2];
    __shared__ int   scnt[2];
    __shared__ ull   skeep[2][TK];
    __shared__ int   sfl, sdk;

    int g = blockIdx.x, s = blockIdx.y;
    int tid = threadIdx.x, lane = tid & 31, w = tid >> 5;
    int len = (((N + SPLIT - 1) / SPLIT) + 3) & ~3;
    int n0 = s * len;
    int n1 = min(N, n0 + len);
    const float2* col = G_IC + g * N;

    if (tid < 2) scnt[tid] = 0;

    // ---------------- phase A: per-thread float top-2, cheap scan ----------------
    float i1 = -1.f, i2 = -1.f;          // two largest masked ious
    float c1 = 3.0e38f, c2 = 3.0e38f;    // two smallest masked costs
    int nfull = n0 + (((n1 - n0) / 4) * 4);
    for (int n = n0 + tid * 4; n < nfull; n += TPB * 4) {
        float4 v0 = *reinterpret_cast<const float4*>(col + n);
        float4 v1 = *reinterpret_cast<const float4*>(col + n + 2);
        unsigned wv = g_valid[n >> 5] >> (n & 31);
        float io[4] = { (wv & 1u) ? v0.x : 0.f, (wv & 2u) ? v0.z : 0.f,
                        (wv & 4u) ? v1.x : 0.f, (wv & 8u) ? v1.z : 0.f };
        float co[4] = { (wv & 1u) ? v0.y : BIG_F, (wv & 2u) ? v0.w : BIG_F,
                        (wv & 4u) ? v1.y : BIG_F, (wv & 8u) ? v1.w : BIG_F };
        #pragma unroll
        for (int k = 0; k < 4; k++) {
            if (io[k] > i2) { if (io[k] > i1) { i2 = i1; i1 = io[k]; } else i2 = io[k]; }
            if (co[k] < c2) { if (co[k] < c1) { c2 = c1; c1 = co[k]; } else c2 = co[k]; }
        }
    }
    for (int n = nfull + tid; n < n1; n += TPB) {
        float2 p = col[n];
        bool vd = (g_valid[n >> 5] >> (n & 31)) & 1u;
        float io = vd ? p.x : 0.f;
        float co = vd ? p.y : BIG_F;
        if (io > i2) { if (io > i1) { i2 = i1; i1 = io; } else i2 = io; }
        if (co < c2) { if (co < c1) { c2 = c1; c1 = co; } else c2 = co; }
    }
    // warp-merge top-2 (once)
    #pragma unroll
    for (int off = 16; off; off >>= 1) {
        float oi1 = __shfl_xor_sync(FULLM, i1, off);
        float oi2 = __shfl_xor_sync(FULLM, i2, off);
        float ni1 = fmaxf(i1, oi1);
        float ni2 = fmaxf(fminf(i1, oi1), fmaxf(i2, oi2));
        i1 = ni1; i2 = ni2;
        float oc1 = __shfl_xor_sync(FULLM, c1, off);
        float oc2 = __shfl_xor_sync(FULLM, c2, off);
        float nc1 = fminf(c1, oc1);
        float nc2 = fminf(fmaxf(c1, oc1), fminf(c2, oc2));
        c1 = nc1; c2 = nc2;
    }
    if (lane == 0) {
        ssamp[0][2 * w] = i1; ssamp[0][2 * w + 1] = i2;
        ssamp[1][2 * w] = c1; ssamp[1][2 * w + 1] = c2;
    }
    __syncthreads();

    // ---------------- threshold: 10th best of 16 samples (ties via lane) --------
    if (w < 2) {
        float v = (lane < 16) ? ssamp[w][lane] : (w ? 3.0e38f : -1.f);
        int cnt = 0;
        #pragma unroll
        for (int j = 0; j < 16; j++) {
            float o = __shfl_sync(FULLM, v, j);
            bool better = (w == 0) ? (o > v) : (o < v);
            cnt += (better || (o == v && j < lane)) ? 1 : 0;
        }
        unsigned sel = __ballot_sync(FULLM, lane < 16 && cnt == 9);
        int l = __ffs(sel) - 1;
        float T = __shfl_sync(FULLM, v, l);
        if (lane == 0) sT[w] = T;
    }
    __syncthreads();
    float Ti = sT[0], Tc = sT[1];

    // ---------------- phase B: compaction (float compares, keys on hit) --------
    for (int n = n0 + tid * 4; n < nfull; n += TPB * 4) {
        float4 v0 = *reinterpret_cast<const float4*>(col + n);
        float4 v1 = *reinterpret_cast<const float4*>(col + n + 2);
        unsigned wv = g_valid[n >> 5] >> (n & 31);
        float io[4] = { (wv & 1u) ? v0.x : 0.f, (wv & 2u) ? v0.z : 0.f,
                        (wv & 4u) ? v1.x : 0.f, (wv & 8u) ? v1.z : 0.f };
        float co[4] = { (wv & 1u) ? v0.y : BIG_F, (wv & 2u) ? v0.w : BIG_F,
                        (wv & 4u) ? v1.y : BIG_F, (wv & 8u) ? v1.w : BIG_F };
        #pragma unroll
        for (int k = 0; k < 4; k++) {
            int ni = n + k;
            if (io[k] >= Ti) {
                ull key = ((ull)(unsigned)~fkey(io[k]) << 32) | (unsigned)ni;
                int p = atomicAdd(&scnt[0], 1); if (p < CAP) sbuf[0][p] = key;
            }
            if (co[k] <= Tc) {
                ull key = ((ull)fkey(co[k]) << 32) | (unsigned)ni;
                int p = atomicAdd(&scnt[1], 1); if (p < CAP) sbuf[1][p] = key;
            }
        }
    }
    for (int n = nfull + tid; n < n1; n += TPB) {
        float2 p = col[n];
        bool vd = (g_valid[n >> 5] >> (n & 31)) & 1u;
        float io = vd ? p.x : 0.f;
        float co = vd ? p.y : BIG_F;
        if (io >= Ti) {
            ull key = ((ull)(unsigned)~fkey(io) << 32) | (unsigned)n;
            int q = atomicAdd(&scnt[0], 1); if (q < CAP) sbuf[0][q] = key;
        }
        if (co <= Tc) {
            ull key = ((ull)fkey(co) << 32) | (unsigned)n;
            int q = atomicAdd(&scnt[1], 1); if (q < CAP) sbuf[1][q] = key;
        }
    }
    __syncthreads();

    // ---------------- exact top-10 extraction from buffers ----------------
    if (w < 2) {
        int cnt = min(scnt[w], CAP);
        ull* buf = sbuf[w];
        for (int r = 0; r < TK; r++) {
            ull m = ~0ULL;
            for (int i = lane; i < cnt; i += 32) m = umin64(m, buf[i]);
            #pragma unroll
            for (int off = 16; off; off >>= 1)
                m = umin64(m, __shfl_xor_sync(FULLM, m, off));
            for (int i = lane; i < cnt; i += 32)
                if (buf[i] == m) buf[i] = ~0ULL;
            if (lane == 0) skeep[w][r] = m;
        }
    }
    __syncthreads();
    if (w == 0 && lane < TK) g_piou [(g * SPLIT + s) * TK + lane] = skeep[0][lane];
    if (w == 1 && lane < TK) g_pcost[(g * SPLIT + s) * TK + lane] = skeep[1][lane];
    __syncthreads();
    if (tid == 0) {
        __threadfence();
        int old = atomicAdd(&g_done[g], 1);
        sfl = (old == (int)gridDim.y - 1);
    }
    __syncthreads();
    if (!sfl) return;

    // ---------------- last block for g: merge 80 keys per list ----------------
    if (w < 2) {
        const ull* src = (w == 0) ? &g_piou[g * TOTK] : &g_pcost[g * TOTK];
        ull k0 = (lane      < TOTK) ? __ldcg(&src[lane])      : ~0ULL;
        ull k1 = (lane + 32 < TOTK) ? __ldcg(&src[lane + 32]) : ~0ULL;
        ull k2 = (lane + 64 < TOTK) ? __ldcg(&src[lane + 64]) : ~0ULL;
        for (int r = 0; r < TK; r++) {
            ull m = umin64(k0, umin64(k1, k2));
            #pragma unroll
            for (int off = 16; off; off >>= 1)
                m = umin64(m, __shfl_xor_sync(FULLM, m, off));
            if (k0 == m) k0 = ~0ULL;
            else if (k1 == m) k1 = ~0ULL;
            else if (k2 == m) k2 = ~0ULL;
            if (lane == 0) skeep[w][r] = m;
        }
    }
    __syncthreads();
    if (tid == 0) {
        float ssum = 0.f;
        #pragma unroll
        for (int r = 0; r < TK; r++) {
            ull k = skeep[0][r];
            if (k != ~0ULL) ssum += unfkey(~(unsigned)(k >> 32));
        }
        int dk = (int)ssum;
        sdk = dk < 1 ? 1 : (dk > TK ? TK : dk);
    }
    __syncthreads();
    if (tid < sdk) {
        ull k = skeep[1][tid];
        if (k != ~0ULL) {
            int n = (int)(unsigned)k;
            atomicAdd(&g_cnt[n], 1);
            atomicMin(&g_mg[n], g);
        }
    }
}

// -------- finalize --------
__global__ void kFinal(float* __restrict__ out, int N, int G) {
    int n = blockIdx.x * blockDim.x + threadIdx.x;
    if (n >= N) return;
    int c = g_cnt[n];
    bool val = (g_valid[n >> 5] >> (n & 31)) & 1u;
    float gi = 0.f, lb = -1.f, io = -INF_F;
    if (c == 1) {
        int g = g_mg[n];
        gi = (float)g; lb = 1.f;
        io = val ? G_IC[g * N + n].x : 0.f;
    } else if (c > 1) {
        lb = 1.f;
        if (!val) { gi = 0.f; io = 0.f; }
        else {
            float best = 3.4e38f; int bg = 0;
            int off = n;
            for (int g = 0; g < G; g++) {
                float v = G_IC[off].y;
                if (v < best) { best = v; bg = g; }
                off += N;
            }
            gi = (float)bg;
            io = G_IC[bg * N + n].x;
        }
    }
    out[n] = gi;
    out[N + n] = lb;
    out[2 * N + n] = io;
}

extern "C" void kernel_launch(void* const* d_in, const int* in_sizes, int n_in,
                              void* d_out, int out_size) {
    const float* ps  = (const float*)d_in[0];
    const float* pri = (const float*)d_in[1];
    const float* dec = (const float*)d_in[2];
    const float* gtb = (const float*)d_in[3];
    const int*   gtl = (const int*)d_in[4];
    int N = in_sizes[1] / 4;
    int G = in_sizes[3] / 4;
    int C = in_sizes[0] / N;
    if (N > NMAX || G > GMAX || C > CMAX) return;
    float* out = (float*)d_out;
    (void)out_size; (void)n_in;

    if (C == 80) {
        kA80<<<(N + 31) / 32, TPB>>>(ps, N);   // fused setup + logits
    } else {
        kSetup<<<(N + TPB - 1) / TPB, TPB>>>(N, G);
        kAgen<<<(N + TPB - 1) / TPB, TPB>>>(ps, N, C);
    }
    dim3 gb((N + TPB - 1) / TPB, (G + GTILE - 1) / GTILE);
    kB<<<gb, TPB>>>(pri, dec, gtb, gtl, N, G);
    dim3 gt(G, SPLIT);
    kTopPart<<<gt, TPB>>>(N);
    kFinal<<<(N + TPB - 1) / TPB, TPB>>>(out, N, G);
}

// round 10
// speedup vs baseline: 1.7490x; 1.0502x over previous
#include <cuda_runtime.h>
#include <stdint.h>

#define NMAX 33600
#define GMAX 128
#define CMAX 80
#define TPB 256
#define TK 10
#define GTILE 16
#define SPLIT 8
#define NW (TPB / 32)
#define CAP 768
#define TOTK (SPLIT * TK)               // 80 partial keys per gt per list
#define EPSF 1e-7f
#define INF_F 100000.0f
#define BIG_F 100000000.0f
#define CRAD 2.5f
#define NWORDS ((NMAX + 31) / 32)
#define FULLM 0xffffffffu

typedef unsigned long long ull;

// ---- scratch as __device__ globals (allocation-free rule) ----
__device__ float    g_D[(size_t)CMAX * NMAX];    // logit(p), class-major
__device__ float    g_sumL1[NMAX];
__device__ float4   g_ic4[(size_t)GMAX * NMAX / 2];   // {iou,cost} pairs, 16B-aligned
#define G_IC ((float2*)g_ic4)
__device__ unsigned g_valid[NWORDS];
__device__ int      g_cnt[NMAX];
__device__ int      g_mg[NMAX];
__device__ ull      g_amin[NMAX];                // row argmin: (fkey(cost)<<32)|g
__device__ int      g_done[GMAX];
__device__ ull      g_piou [GMAX * TOTK];
__device__ ull      g_pcost[GMAX * TOTK];

// monotone float->uint (ascending order preserved)
__device__ __forceinline__ unsigned fkey(float f) {
    unsigned u = __float_as_uint(f);
    return (u & 0x80000000u) ? ~u : (u | 0x80000000u);
}
__device__ __forceinline__ float unfkey(unsigned k) {
    unsigned u = (k & 0x80000000u) ? (k ^ 0x80000000u) : ~k;
    return __uint_as_float(u);
}

__device__ __forceinline__ ull umin64(ull a, ull b) { return a < b ? a : b; }

// -------- kA80: fused init + logit + sumL1 (C==80 fast path) --------
__global__ void __launch_bounds__(TPB) kA80(const float* __restrict__ ps, int N) {
    __shared__ float s[32 * 81];
    __shared__ float part[8][33];
    int tid = threadIdx.x;
    int n0 = blockIdx.x * 32;
    int rows = min(32, N - n0);

    // fused setup (indices disjoint from compute outputs)
    if (tid < 32 && tid < rows) {
        g_cnt[n0 + tid] = 0;
        g_mg[n0 + tid] = 0x7fffffff;
        g_amin[n0 + tid] = ~0ULL;
    }
    if (tid == 32) g_valid[blockIdx.x] = 0u;
    if (tid == 33 && (int)blockIdx.x < GMAX) g_done[blockIdx.x] = 0;

    for (int i = tid; i < rows * 80; i += TPB) {
        int r = i / 80, c = i - r * 80;
        s[r * 81 + c] = ps[n0 * 80 + i];
    }
    __syncthreads();
    int lane = tid & 31, w = tid >> 5;
    int n = n0 + lane;
    if (lane < rows) {
        float prod0 = 1.f, prod1 = 1.f;
        #pragma unroll
        for (int j = 0; j < 10; j++) {
            int c = w + j * 8;
            float p = s[lane * 81 + c];
            float q = 1.f - p;
            if (j < 5) prod0 *= q; else prod1 *= q;
            g_D[c * N + n] = __logf(__fdividef(p, q));
        }
        part[w][lane] = __logf(prod0) + __logf(prod1);
    }
    __syncthreads();
    if (w == 0 && lane < rows) {
        float ssum = 0.f;
        #pragma unroll
        for (int k = 0; k < 8; k++) ssum += part[k][lane];
        g_sumL1[n] = ssum;
    }
}

// -------- generic fallbacks (not used for this problem's shapes) --------
__global__ void kSetup(int N, int G) {
    int i = blockIdx.x * blockDim.x + threadIdx.x;
    if (i < N) { g_cnt[i] = 0; g_mg[i] = 0x7fffffff; g_amin[i] = ~0ULL; }
    if (i < NWORDS) g_valid[i] = 0u;
    if (i < GMAX) g_done[i] = 0;
}
__global__ void kAgen(const float* __restrict__ ps, int N, int C) {
    int n = blockIdx.x * blockDim.x + threadIdx.x;
    if (n >= N) return;
    float ssum = 0.f;
    for (int c = 0; c < C; c++) {
        float p = ps[(size_t)n * C + c];
        float L  = fmaxf(__logf(p), -100.f);
        float L1 = fmaxf(__logf(1.f - p), -100.f);
        g_D[c * N + n] = L - L1;
        ssum += L1;
    }
    g_sumL1[n] = ssum;
}

// -------- kB: pairwise IoU + cost + local row-argmin --------
__global__ void __launch_bounds__(TPB) kB(
    const float* __restrict__ priors, const float* __restrict__ dec,
    const float* __restrict__ gtb, const int* __restrict__ gtl,
    int N, int G)
{
    __shared__ float4 sg0[GTILE];
    __shared__ float4 sg1[GTILE];
    int tid = threadIdx.x;
    int g0 = blockIdx.y * GTILE;
    int gcnt = min(GTILE, G - g0);
    if (tid < gcnt) {
        int g = g0 + tid;
        float x0 = gtb[4*g+0], y0 = gtb[4*g+1], x1 = gtb[4*g+2], y1 = gtb[4*g+3];
        sg0[tid] = make_float4(x0, y0, x1, y1);
        float gcx = (x0 + x1) * 0.5f, gcy = (y0 + y1) * 0.5f;
        float area = fmaxf(x1 - x0, 0.f) * fmaxf(y1 - y0, 0.f);
        sg1[tid] = make_float4(gcx, gcy, area, __int_as_float(gtl[g] * N));
    }
    __syncthreads();

    int n = blockIdx.x * blockDim.x + tid;
    if (n >= N) return;
    float4 pq = ((const float4*)priors)[n];
    float px = pq.x, py = pq.y;
    float a1 = px + CRAD * pq.z, a2 = px - CRAD * pq.z;
    float b1 = py + CRAD * pq.w, b2 = py - CRAD * pq.w;
    float4 dq = ((const float4*)dec)[n];
    float dx0 = dq.x, dy0 = dq.y, dx1 = dq.z, dy1 = dq.w;
    float aa = fmaxf(dx1 - dx0, 0.f) * fmaxf(dy1 - dy0, 0.f);
    float sL1 = g_sumL1[n];

    bool vacc = false;
    ull kmin = ~0ULL;
    int base = g0 * N + n;                 // int offset, bumped by N per gi
    if (gcnt == GTILE) {
        #pragma unroll
        for (int gi = 0; gi < GTILE; gi++) {
            float4 q0 = sg0[gi];
            float4 q1 = sg1[gi];
            float m1 = fminf(fminf(px - q0.x, py - q0.y), fminf(q0.z - px, q0.w - py));
            float m2 = fminf(fminf(a1 - q1.x, b1 - q1.y), fminf(q1.x - a2, q1.y - b2));
            bool ing = m1 > 0.f, inc = m2 > 0.f;
            vacc = vacc || ing || inc;
            float w = fmaxf(fminf(dx1, q0.z) - fmaxf(dx0, q0.x), 0.f);
            float h = fmaxf(fminf(dy1, q0.w) - fmaxf(dy0, q0.y), 0.f);
            float inter = w * h;
            float uni = fmaxf(aa + q1.z - inter, EPSF);
            float iou = __fdividef(inter, uni);
            float cls = -g_D[__float_as_int(q1.w) + n] - sL1;
            float cost = cls - 3.0f * __logf(iou + EPSF);
            if (!(ing && inc)) cost += INF_F;
            G_IC[base] = make_float2(iou, cost);
            base += N;
            ull key = ((ull)fkey(cost) << 32) | (unsigned)(g0 + gi);
            kmin = umin64(kmin, key);
        }
    } else {
        for (int gi = 0; gi < gcnt; gi++) {
            float4 q0 = sg0[gi];
            float4 q1 = sg1[gi];
            float m1 = fminf(fminf(px - q0.x, py - q0.y), fminf(q0.z - px, q0.w - py));
            float m2 = fminf(fminf(a1 - q1.x, b1 - q1.y), fminf(q1.x - a2, q1.y - b2));
            bool ing = m1 > 0.f, inc = m2 > 0.f;
            vacc = vacc || ing || inc;
            float w = fmaxf(fminf(dx1, q0.z) - fmaxf(dx0, q0.x), 0.f);
            float h = fmaxf(fminf(dy1, q0.w) - fmaxf(dy0, q0.y), 0.f);
            float inter = w * h;
            float uni = fmaxf(aa + q1.z - inter, EPSF);
            float iou = __fdividef(inter, uni);
            float cls = -g_D[__float_as_int(q1.w) + n] - sL1;
            float cost = cls - 3.0f * __logf(iou + EPSF);
            if (!(ing && inc)) cost += INF_F;
            G_IC[base] = make_float2(iou, cost);
            base += N;
            ull key = ((ull)fkey(cost) << 32) | (unsigned)(g0 + gi);
            kmin = umin64(kmin, key);
        }
    }
    atomicMin(&g_amin[n], kmin);
    unsigned m = __ballot_sync(__activemask(), vacc);
    if ((tid & 31) == 0 && m) atomicOr(&g_valid[n >> 5], m);
}

// -------- kTopPart: grid (G, SPLIT). float-threshold sampling + compaction.
//          Last block per g merges + dynamic_k + atomics. ----
__global__ void __launch_bounds__(TPB) kTopPart(int N) {
    __shared__ ull   sbuf[2][CAP];
    __shared__ float ssamp[2][16];
    __shared__ float sT[2];
    __shared__ int   scnt[2];
    __shared__ ull   skeep[2][TK];
    __shared__ int   sfl, sdk;

    int g = blockIdx.x, s = blockIdx.y;
    int tid = threadIdx.x, lane = tid & 31, w = tid >> 5;
    int len = (((N + SPLIT - 1) / SPLIT) + 3) & ~3;
    int n0 = s * len;
    int n1 = min(N, n0 + len);
    const float2* col = G_IC + g * N;

    if (tid < 2) scnt[tid] = 0;

    // ---------------- phase A: per-thread float top-2, cheap scan ----------------
    float i1 = -1.f, i2 = -1.f;          // two largest masked ious
    float c1 = 3.0e38f, c2 = 3.0e38f;    // two smallest masked costs
    int nfull = n0 + (((n1 - n0) / 4) * 4);
    for (int n = n0 + tid * 4; n < nfull; n += TPB * 4) {
        float4 v0 = *reinterpret_cast<const float4*>(col + n);
        float4 v1 = *reinterpret_cast<const float4*>(col + n + 2);
        unsigned wv = g_valid[n >> 5] >> (n & 31);
        float io[4] = { (wv & 1u) ? v0.x : 0.f, (wv & 2u) ? v0.z : 0.f,
                        (wv & 4u) ? v1.x : 0.f, (wv & 8u) ? v1.z : 0.f };
        float co[4] = { (wv & 1u) ? v0.y : BIG_F, (wv & 2u) ? v0.w : BIG_F,
                        (wv & 4u) ? v1.y : BIG_F, (wv & 8u) ? v1.w : BIG_F };
        #pragma unroll
        for (int k = 0; k < 4; k++) {
            if (io[k] > i2) { if (io[k] > i1) { i2 = i1; i1 = io[k]; } else i2 = io[k]; }
            if (co[k] < c2) { if (co[k] < c1) { c2 = c1; c1 = co[k]; } else c2 = co[k]; }
        }
    }
    for (int n = nfull + tid; n < n1; n += TPB) {
        float2 p = col[n];
        bool vd = (g_valid[n >> 5] >> (n & 31)) & 1u;
        float io = vd ? p.x : 0.f;
        float co = vd ? p.y : BIG_F;
        if (io > i2) { if (io > i1) { i2 = i1; i1 = io; } else i2 = io; }
        if (co < c2) { if (co < c1) { c2 = c1; c1 = co; } else c2 = co; }
    }
    // warp-merge top-2 (once)
    #pragma unroll
    for (int off = 16; off; off >>= 1) {
        float oi1 = __shfl_xor_sync(FULLM, i1, off);
        float oi2 = __shfl_xor_sync(FULLM, i2, off);
        float ni1 = fmaxf(i1, oi1);
        float ni2 = fmaxf(fminf(i1, oi1), fmaxf(i2, oi2));
        i1 = ni1; i2 = ni2;
        float oc1 = __shfl_xor_sync(FULLM, c1, off);
        float oc2 = __shfl_xor_sync(FULLM, c2, off);
        float nc1 = fminf(c1, oc1);
        float nc2 = fminf(fmaxf(c1, oc1), fminf(c2, oc2));
        c1 = nc1; c2 = nc2;
    }
    if (lane == 0) {
        ssamp[0][2 * w] = i1; ssamp[0][2 * w + 1] = i2;
        ssamp[1][2 * w] = c1; ssamp[1][2 * w + 1] = c2;
    }
    __syncthreads();

    // ---------------- threshold: 10th best of 16 samples (ties via lane) --------
    if (w < 2) {
        float v = (lane < 16) ? ssamp[w][lane] : (w ? 3.0e38f : -1.f);
        int cnt = 0;
        #pragma unroll
        for (int j = 0; j < 16; j++) {
            float o = __shfl_sync(FULLM, v, j);
            bool better = (w == 0) ? (o > v) : (o < v);
            cnt += (better || (o == v && j < lane)) ? 1 : 0;
        }
        unsigned sel = __ballot_sync(FULLM, lane < 16 && cnt == 9);
        int l = __ffs(sel) - 1;
        float T = __shfl_sync(FULLM, v, l);
        if (lane == 0) sT[w] = T;
    }
    __syncthreads();
    float Ti = sT[0], Tc = sT[1];

    // ---------------- phase B: compaction (float compares, keys on hit) --------
    for (int n = n0 + tid * 4; n < nfull; n += TPB * 4) {
        float4 v0 = *reinterpret_cast<const float4*>(col + n);
        float4 v1 = *reinterpret_cast<const float4*>(col + n + 2);
        unsigned wv = g_valid[n >> 5] >> (n & 31);
        float io[4] = { (wv & 1u) ? v0.x : 0.f, (wv & 2u) ? v0.z : 0.f,
                        (wv & 4u) ? v1.x : 0.f, (wv & 8u) ? v1.z : 0.f };
        float co[4] = { (wv & 1u) ? v0.y : BIG_F, (wv & 2u) ? v0.w : BIG_F,
                        (wv & 4u) ? v1.y : BIG_F, (wv & 8u) ? v1.w : BIG_F };
        #pragma unroll
        for (int k = 0; k < 4; k++) {
            int ni = n + k;
            if (io[k] >= Ti) {
                ull key = ((ull)(unsigned)~fkey(io[k]) << 32) | (unsigned)ni;
                int p = atomicAdd(&scnt[0], 1); if (p < CAP) sbuf[0][p] = key;
            }
            if (co[k] <= Tc) {
                ull key = ((ull)fkey(co[k]) << 32) | (unsigned)ni;
                int p = atomicAdd(&scnt[1], 1); if (p < CAP) sbuf[1][p] = key;
            }
        }
    }
    for (int n = nfull + tid; n < n1; n += TPB) {
        float2 p = col[n];
        bool vd = (g_valid[n >> 5] >> (n & 31)) & 1u;
        float io = vd ? p.x : 0.f;
        float co = vd ? p.y : BIG_F;
        if (io >= Ti) {
            ull key = ((ull)(unsigned)~fkey(io) << 32) | (unsigned)n;
            int q = atomicAdd(&scnt[0], 1); if (q < CAP) sbuf[0][q] = key;
        }
        if (co <= Tc) {
            ull key = ((ull)fkey(co) << 32) | (unsigned)n;
            int q = atomicAdd(&scnt[1], 1); if (q < CAP) sbuf[1][q] = key;
        }
    }
    __syncthreads();

    // ---------------- exact top-10 extraction from buffers ----------------
    if (w < 2) {
        int cnt = min(scnt[w], CAP);
        ull* buf = sbuf[w];
        for (int r = 0; r < TK; r++) {
            ull m = ~0ULL;
            for (int i = lane; i < cnt; i += 32) m = umin64(m, buf[i]);
            #pragma unroll
            for (int off = 16; off; off >>= 1)
                m = umin64(m, __shfl_xor_sync(FULLM, m, off));
            for (int i = lane; i < cnt; i += 32)
                if (buf[i] == m) buf[i] = ~0ULL;
            if (lane == 0) skeep[w][r] = m;
        }
    }
    __syncthreads();
    if (w == 0 && lane < TK) g_piou [(g * SPLIT + s) * TK + lane] = skeep[0][lane];
    if (w == 1 && lane < TK) g_pcost[(g * SPLIT + s) * TK + lane] = skeep[1][lane];
    __syncthreads();
    if (tid == 0) {
        __threadfence();
        int old = atomicAdd(&g_done[g], 1);
        sfl = (old == (int)gridDim.y - 1);
    }
    __syncthreads();
    if (!sfl) return;

    // ---------------- last block for g: merge 80 keys per list ----------------
    if (w < 2) {
        const ull* src = (w == 0) ? &g_piou[g * TOTK] : &g_pcost[g * TOTK];
        ull k0 = (lane      < TOTK) ? __ldcg(&src[lane])      : ~0ULL;
        ull k1 = (lane + 32 < TOTK) ? __ldcg(&src[lane + 32]) : ~0ULL;
        ull k2 = (lane + 64 < TOTK) ? __ldcg(&src[lane + 64]) : ~0ULL;
        for (int r = 0; r < TK; r++) {
            ull m = umin64(k0, umin64(k1, k2));
            #pragma unroll
            for (int off = 16; off; off >>= 1)
                m = umin64(m, __shfl_xor_sync(FULLM, m, off));
            if (k0 == m) k0 = ~0ULL;
            else if (k1 == m) k1 = ~0ULL;
            else if (k2 == m) k2 = ~0ULL;
            if (lane == 0) skeep[w][r] = m;
        }
    }
    __syncthreads();
    if (tid == 0) {
        float ssum = 0.f;
        #pragma unroll
        for (int r = 0; r < TK; r++) {
            ull k = skeep[0][r];
            if (k != ~0ULL) ssum += unfkey(~(unsigned)(k >> 32));
        }
        int dk = (int)ssum;
        sdk = dk < 1 ? 1 : (dk > TK ? TK : dk);
    }
    __syncthreads();
    if (tid < sdk) {
        ull k = skeep[1][tid];
        if (k != ~0ULL) {
            int n = (int)(unsigned)k;
            atomicAdd(&g_cnt[n], 1);
            atomicMin(&g_mg[n], g);
        }
    }
}

// -------- finalize: no row scan; uses precomputed row argmin --------
__global__ void kFinal(float* __restrict__ out, int N, int G) {
    int n = blockIdx.x * blockDim.x + threadIdx.x;
    if (n >= N) return;
    int c = g_cnt[n];
    bool val = (g_valid[n >> 5] >> (n & 31)) & 1u;
    float gi = 0.f, lb = -1.f, io = -INF_F;
    if (c == 1) {
        int g = g_mg[n];
        gi = (float)g; lb = 1.f;
        io = val ? G_IC[g * N + n].x : 0.f;
    } else if (c > 1) {
        lb = 1.f;
        if (!val) { gi = 0.f; io = 0.f; }
        else {
            int bg = (int)(unsigned)g_amin[n];
            gi = (float)bg;
            io = G_IC[bg * N + n].x;
        }
    }
    out[n] = gi;
    out[N + n] = lb;
    out[2 * N + n] = io;
}

extern "C" void kernel_launch(void* const* d_in, const int* in_sizes, int n_in,
                              void* d_out, int out_size) {
    const float* ps  = (const float*)d_in[0];
    const float* pri = (const float*)d_in[1];
    const float* dec = (const float*)d_in[2];
    const float* gtb = (const float*)d_in[3];
    const int*   gtl = (const int*)d_in[4];
    int N = in_sizes[1] / 4;
    int G = in_sizes[3] / 4;
    int C = in_sizes[0] / N;
    if (N > NMAX || G > GMAX || C > CMAX) return;
    float* out = (float*)d_out;
    (void)out_size; (void)n_in;

    if (C == 80) {
        kA80<<<(N + 31) / 32, TPB>>>(ps, N);   // fused setup + logits
    } else {
        kSetup<<<(N + TPB - 1) / TPB, TPB>>>(N, G);
        kAgen<<<(N + TPB - 1) / TPB, TPB>>>(ps, N, C);
    }
    dim3 gb((N + TPB - 1) / TPB, (G + GTILE - 1) / GTILE);
    kB<<<gb, TPB>>>(pri, dec, gtb, gtl, N, G);
    dim3 gt(G, SPLIT);
    kTopPart<<<gt, TPB>>>(N);
    kFinal<<<(N + TPB - 1) / TPB, TPB>>>(out, N, G);
}